// round 1
// baseline (speedup 1.0000x reference)
#include <cuda_runtime.h>

typedef unsigned long long ull;

#define TPB 256
#define BM  64
#define BN  128
#define KK  128
#define SAS 130   // sA row stride in floats (odd-ish pad: avoids bank conflicts on a-reads)

static const int MAXN = 50000;

// scratch (no allocations allowed)
__device__ float g_Q [MAXN * 128];
__device__ float g_K [MAXN * 128];
__device__ float g_V [MAXN * 128];
__device__ float g_wV[MAXN * 128];
__device__ float g_z [MAXN * 8];

// ---------- packed f32x2 helpers ----------
__device__ __forceinline__ ull pk(float lo, float hi) {
    ull r; asm("mov.b64 %0, {%1, %2};" : "=l"(r) : "f"(lo), "f"(hi)); return r;
}
__device__ __forceinline__ void fma2(ull& d, ull a, ull b) {
    asm("fma.rn.f32x2 %0, %1, %2, %0;" : "+l"(d) : "l"(a), "l"(b));
}
__device__ __forceinline__ void upk(ull v, float& lo, float& hi) {
    asm("mov.b64 {%0, %1}, %2;" : "=f"(lo), "=f"(hi) : "l"(v));
}

// ---------- shared GEMM pieces: C[BM x 128] = A_tile[BM x 128] @ W[128 x 128] ----------
__device__ __forceinline__ void load_tiles(const float* __restrict__ A, int rows, int mb,
                                           const float* __restrict__ W,
                                           float* sA, float* sB, int tid) {
    // A tile: BM x 128 -> sA[m*SAS + k]; coalesced float4 global reads
    #pragma unroll
    for (int i = 0; i < 8; i++) {            // 64 rows * 32 float4 / 256 thr
        int idx = i * TPB + tid;
        int m   = idx >> 5;
        int c4  = (idx & 31) << 2;
        int row = mb + m;
        float4 val = make_float4(0.f, 0.f, 0.f, 0.f);
        if (row < rows) val = *reinterpret_cast<const float4*>(A + (long)row * 128 + c4);
        float* d = sA + m * SAS + c4;
        d[0] = val.x; d[1] = val.y; d[2] = val.z; d[3] = val.w;
    }
    // W tile: 128 x 128 -> sB[k*128 + n]; natural layout, conflict free
    #pragma unroll
    for (int i = 0; i < 16; i++) {           // 128 rows * 32 float4 / 256 thr
        int idx = i * TPB + tid;
        int k   = idx >> 5;
        int c4  = (idx & 31) << 2;
        *reinterpret_cast<float4*>(sB + k * BN + c4) =
            *reinterpret_cast<const float4*>(W + k * BN + c4);
    }
}

// thread tile: 4 rows (m) x 8 cols (n) accumulated as 4x4 f32x2 pairs
__device__ __forceinline__ void gemm_core(const float* sA, const float* sB,
                                          int ty, int tx, ull acc[4][4]) {
    const int m0 = ty * 4;
    const int n0 = tx * 8;
    #pragma unroll 8
    for (int k = 0; k < KK; k++) {
        float a0 = sA[(m0 + 0) * SAS + k];
        float a1 = sA[(m0 + 1) * SAS + k];
        float a2 = sA[(m0 + 2) * SAS + k];
        float a3 = sA[(m0 + 3) * SAS + k];
        float4 b0 = *reinterpret_cast<const float4*>(sB + k * BN + n0);
        float4 b1 = *reinterpret_cast<const float4*>(sB + k * BN + n0 + 4);
        ull bp0 = pk(b0.x, b0.y), bp1 = pk(b0.z, b0.w);
        ull bp2 = pk(b1.x, b1.y), bp3 = pk(b1.z, b1.w);
        ull ap;
        ap = pk(a0, a0);
        fma2(acc[0][0], ap, bp0); fma2(acc[0][1], ap, bp1);
        fma2(acc[0][2], ap, bp2); fma2(acc[0][3], ap, bp3);
        ap = pk(a1, a1);
        fma2(acc[1][0], ap, bp0); fma2(acc[1][1], ap, bp1);
        fma2(acc[1][2], ap, bp2); fma2(acc[1][3], ap, bp3);
        ap = pk(a2, a2);
        fma2(acc[2][0], ap, bp0); fma2(acc[2][1], ap, bp1);
        fma2(acc[2][2], ap, bp2); fma2(acc[2][3], ap, bp3);
        ap = pk(a3, a3);
        fma2(acc[3][0], ap, bp0); fma2(acc[3][1], ap, bp1);
        fma2(acc[3][2], ap, bp2); fma2(acc[3][3], ap, bp3);
    }
}

// ---------- kernel 0: zero accumulators ----------
__global__ void zero_kernel(int N) {
    int i = blockIdx.x * blockDim.x + threadIdx.x;
    if (i < N * 128) g_wV[i] = 0.f;
    if (i < N * 8)   g_z[i]  = 0.f;
}

// ---------- kernel 1: Q/K/V node projections (blockIdx.y selects which) ----------
__global__ void __launch_bounds__(TPB, 2)
node_qkv_kernel(const float* __restrict__ v,
                const float* __restrict__ Wq, const float* __restrict__ bq,
                const float* __restrict__ Wk, const float* __restrict__ bk,
                const float* __restrict__ Wv, const float* __restrict__ bv,
                int N) {
    extern __shared__ float smem[];
    float* sA = smem;
    float* sB = smem + BM * SAS;
    int tid = threadIdx.x;
    int tx = tid & 15, ty = tid >> 4;

    const float* W; const float* bias; float* out;
    if      (blockIdx.y == 0) { W = Wq; bias = bq; out = g_Q; }
    else if (blockIdx.y == 1) { W = Wk; bias = bk; out = g_K; }
    else                      { W = Wv; bias = bv; out = g_V; }

    int mb = blockIdx.x * BM;
    load_tiles(v, N, mb, W, sA, sB, tid);
    __syncthreads();

    ull acc[4][4];
    #pragma unroll
    for (int i = 0; i < 4; i++)
        #pragma unroll
        for (int j = 0; j < 4; j++) acc[i][j] = 0ull;

    gemm_core(sA, sB, ty, tx, acc);

    int n0 = tx * 8;
    float bl[8];
    #pragma unroll
    for (int j = 0; j < 8; j++) bl[j] = bias[n0 + j];

    #pragma unroll
    for (int r = 0; r < 4; r++) {
        int row = mb + ty * 4 + r;
        if (row < N) {
            float o[8];
            upk(acc[r][0], o[0], o[1]); upk(acc[r][1], o[2], o[3]);
            upk(acc[r][2], o[4], o[5]); upk(acc[r][3], o[6], o[7]);
            #pragma unroll
            for (int j = 0; j < 8; j++) o[j] += bl[j];
            float4* dst = reinterpret_cast<float4*>(out + (long)row * 128 + n0);
            dst[0] = make_float4(o[0], o[1], o[2], o[3]);
            dst[1] = make_float4(o[4], o[5], o[6], o[7]);
        }
    }
}

// ---------- kernel 2: edge projection + score + e_out + softmax numerator + scatter ----------
__global__ void __launch_bounds__(TPB, 2)
edge_kernel(const float* __restrict__ e,
            const float* __restrict__ We, const float* __restrict__ be,
            const float* __restrict__ envelope,
            const int* __restrict__ src, const int* __restrict__ dst,
            float* __restrict__ eout, int E) {
    extern __shared__ float smem[];
    float* sA = smem;
    float* sB = smem + BM * SAS;
    int tid = threadIdx.x;
    int tx = tid & 15, ty = tid >> 4;

    int mb = blockIdx.x * BM;
    load_tiles(e, E, mb, We, sA, sB, tid);
    __syncthreads();

    ull acc[4][4];
    #pragma unroll
    for (int i = 0; i < 4; i++)
        #pragma unroll
        for (int j = 0; j < 4; j++) acc[i][j] = 0ull;

    gemm_core(sA, sB, ty, tx, acc);

    int n0 = tx * 8;
    int head = tx >> 1;
    float bl[8];
    #pragma unroll
    for (int j = 0; j < 8; j++) bl[j] = be[n0 + j];

    #pragma unroll
    for (int r = 0; r < 4; r++) {
        int ed  = mb + ty * 4 + r;
        int edc = (ed < E) ? ed : (E - 1);   // clamped so all lanes stay active for shfl
        int si = src[edc];
        int di = dst[edc];

        float p[8];
        upk(acc[r][0], p[0], p[1]); upk(acc[r][1], p[2], p[3]);
        upk(acc[r][2], p[4], p[5]); upk(acc[r][3], p[6], p[7]);
        #pragma unroll
        for (int j = 0; j < 8; j++) p[j] += bl[j];

        const float4* Kp = reinterpret_cast<const float4*>(g_K + (long)si * 128 + n0);
        const float4* Qp = reinterpret_cast<const float4*>(g_Q + (long)di * 128 + n0);
        float4 k0 = Kp[0], k1 = Kp[1];
        float4 q0 = Qp[0], q1 = Qp[1];

        float sc[8];
        sc[0] = k0.x * q0.x * 0.25f * p[0];
        sc[1] = k0.y * q0.y * 0.25f * p[1];
        sc[2] = k0.z * q0.z * 0.25f * p[2];
        sc[3] = k0.w * q0.w * 0.25f * p[3];
        sc[4] = k1.x * q1.x * 0.25f * p[4];
        sc[5] = k1.y * q1.y * 0.25f * p[5];
        sc[6] = k1.z * q1.z * 0.25f * p[6];
        sc[7] = k1.w * q1.w * 0.25f * p[7];

        float part = ((sc[0] + sc[1]) + (sc[2] + sc[3])) + ((sc[4] + sc[5]) + (sc[6] + sc[7]));
        part += __shfl_xor_sync(0xFFFFFFFFu, part, 1);   // pair-sum across the 16-col head
        float s = __expf(fminf(fmaxf(part, -5.f), 5.f));

        if (ed < E) {
            // explicit edge feature output (pre-exp)
            float4* ep = reinterpret_cast<float4*>(eout + (long)ed * 128 + n0);
            ep[0] = make_float4(sc[0], sc[1], sc[2], sc[3]);
            ep[1] = make_float4(sc[4], sc[5], sc[6], sc[7]);

            float env = envelope[ed];
            float es  = env * s;
            const float4* Vp = reinterpret_cast<const float4*>(g_V + (long)si * 128 + n0);
            float4 v0 = Vp[0], v1 = Vp[1];
            float* w = g_wV + (long)di * 128 + n0;
            atomicAdd(w + 0, v0.x * es);
            atomicAdd(w + 1, v0.y * es);
            atomicAdd(w + 2, v0.z * es);
            atomicAdd(w + 3, v0.w * es);
            atomicAdd(w + 4, v1.x * es);
            atomicAdd(w + 5, v1.y * es);
            atomicAdd(w + 6, v1.z * es);
            atomicAdd(w + 7, v1.w * es);
            if ((tx & 1) == 0) atomicAdd(g_z + (long)di * 8 + head, s);
        }
    }
}

// ---------- kernel 3: normalize ----------
__global__ void norm_kernel(float* __restrict__ vout, int N) {
    int i = blockIdx.x * blockDim.x + threadIdx.x;
    if (i < N * 128) {
        int n = i >> 7;
        int c = i & 127;
        vout[i] = g_wV[i] / (g_z[n * 8 + (c >> 4)] + 1e-6f);
    }
}

extern "C" void kernel_launch(void* const* d_in, const int* in_sizes, int n_in,
                              void* d_out, int out_size) {
    const float* v        = (const float*)d_in[0];
    const float* e        = (const float*)d_in[1];
    const float* envelope = (const float*)d_in[2];
    const float* Wq       = (const float*)d_in[3];
    const float* bq       = (const float*)d_in[4];
    const float* Wk       = (const float*)d_in[5];
    const float* bk       = (const float*)d_in[6];
    const float* Wv       = (const float*)d_in[7];
    const float* bv       = (const float*)d_in[8];
    const float* We       = (const float*)d_in[9];
    const float* be       = (const float*)d_in[10];
    const int*   src      = (const int*)d_in[11];
    const int*   dst      = (const int*)d_in[12];

    int N = in_sizes[0] / 128;
    int E = in_sizes[11];

    float* out  = (float*)d_out;
    float* vout = out;                       // [N,H,D] first
    float* eout = out + (long)N * 128;       // [E,H,D] second

    size_t smem = (size_t)(BM * SAS + KK * BN) * sizeof(float);  // ~98.8 KB
    cudaFuncSetAttribute(node_qkv_kernel, cudaFuncAttributeMaxDynamicSharedMemorySize, (int)smem);
    cudaFuncSetAttribute(edge_kernel,     cudaFuncAttributeMaxDynamicSharedMemorySize, (int)smem);

    zero_kernel<<<(N * 128 + 255) / 256, 256>>>(N);
    node_qkv_kernel<<<dim3((N + BM - 1) / BM, 3), TPB, smem>>>(v, Wq, bq, Wk, bk, Wv, bv, N);
    edge_kernel<<<(E + BM - 1) / BM, TPB, smem>>>(e, We, be, envelope, src, dst, eout, E);
    norm_kernel<<<(N * 128 + 255) / 256, 256>>>(vout, N);
}

// round 2
// speedup vs baseline: 1.1461x; 1.1461x over previous
#include <cuda_runtime.h>

typedef unsigned long long ull;

#define TPB 256
#define BM  64
#define BN  128
#define KK  128
#define SAS 130   // sA row stride in floats (pad: avoids bank conflicts on a-reads)

static const int MAXN = 50000;

// scratch (no allocations allowed)
__device__ float g_Q [MAXN * 128];
__device__ float g_K [MAXN * 128];
__device__ float g_V [MAXN * 128];
__device__ float g_wV[MAXN * 128];
__device__ float g_z [MAXN * 8];

// ---------- packed f32x2 helpers ----------
__device__ __forceinline__ ull pk(float lo, float hi) {
    ull r; asm("mov.b64 %0, {%1, %2};" : "=l"(r) : "f"(lo), "f"(hi)); return r;
}
__device__ __forceinline__ void fma2(ull& d, ull a, ull b) {
    asm("fma.rn.f32x2 %0, %1, %2, %0;" : "+l"(d) : "l"(a), "l"(b));
}
__device__ __forceinline__ void upk(ull v, float& lo, float& hi) {
    asm("mov.b64 {%0, %1}, %2;" : "=f"(lo), "=f"(hi) : "l"(v));
}

// vector reduction: one 16-byte atomic add (element-wise) per op
__device__ __forceinline__ void red_v4(float* p, float a, float b, float c, float d) {
    asm volatile("red.global.add.v4.f32 [%0], {%1, %2, %3, %4};"
                 :: "l"(p), "f"(a), "f"(b), "f"(c), "f"(d) : "memory");
}

// ---------- shared GEMM pieces: C[BM x 128] = A_tile[BM x 128] @ W[128 x 128] ----------
__device__ __forceinline__ void load_tiles(const float* __restrict__ A, int rows, int mb,
                                           const float* __restrict__ W,
                                           float* sA, float* sB, int tid) {
    #pragma unroll
    for (int i = 0; i < 8; i++) {            // 64 rows * 32 float4 / 256 thr
        int idx = i * TPB + tid;
        int m   = idx >> 5;
        int c4  = (idx & 31) << 2;
        int row = mb + m;
        float4 val = make_float4(0.f, 0.f, 0.f, 0.f);
        if (row < rows) val = *reinterpret_cast<const float4*>(A + (long)row * 128 + c4);
        float* d = sA + m * SAS + c4;
        d[0] = val.x; d[1] = val.y; d[2] = val.z; d[3] = val.w;
    }
    #pragma unroll
    for (int i = 0; i < 16; i++) {           // 128 rows * 32 float4 / 256 thr
        int idx = i * TPB + tid;
        int k   = idx >> 5;
        int c4  = (idx & 31) << 2;
        *reinterpret_cast<float4*>(sB + k * BN + c4) =
            *reinterpret_cast<const float4*>(W + k * BN + c4);
    }
}

// thread tile: 4 rows (m) x 8 cols (n) accumulated as 4x4 f32x2 pairs
__device__ __forceinline__ void gemm_core(const float* sA, const float* sB,
                                          int ty, int tx, ull acc[4][4]) {
    const int m0 = ty * 4;
    const int n0 = tx * 8;
    #pragma unroll 8
    for (int k = 0; k < KK; k++) {
        float a0 = sA[(m0 + 0) * SAS + k];
        float a1 = sA[(m0 + 1) * SAS + k];
        float a2 = sA[(m0 + 2) * SAS + k];
        float a3 = sA[(m0 + 3) * SAS + k];
        float4 b0 = *reinterpret_cast<const float4*>(sB + k * BN + n0);
        float4 b1 = *reinterpret_cast<const float4*>(sB + k * BN + n0 + 4);
        ull bp0 = pk(b0.x, b0.y), bp1 = pk(b0.z, b0.w);
        ull bp2 = pk(b1.x, b1.y), bp3 = pk(b1.z, b1.w);
        ull ap;
        ap = pk(a0, a0);
        fma2(acc[0][0], ap, bp0); fma2(acc[0][1], ap, bp1);
        fma2(acc[0][2], ap, bp2); fma2(acc[0][3], ap, bp3);
        ap = pk(a1, a1);
        fma2(acc[1][0], ap, bp0); fma2(acc[1][1], ap, bp1);
        fma2(acc[1][2], ap, bp2); fma2(acc[1][3], ap, bp3);
        ap = pk(a2, a2);
        fma2(acc[2][0], ap, bp0); fma2(acc[2][1], ap, bp1);
        fma2(acc[2][2], ap, bp2); fma2(acc[2][3], ap, bp3);
        ap = pk(a3, a3);
        fma2(acc[3][0], ap, bp0); fma2(acc[3][1], ap, bp1);
        fma2(acc[3][2], ap, bp2); fma2(acc[3][3], ap, bp3);
    }
}

// ---------- kernel 0: zero accumulators ----------
__global__ void zero_kernel(int N) {
    int i = blockIdx.x * blockDim.x + threadIdx.x;
    if (i < N * 128) g_wV[i] = 0.f;
    if (i < N * 8)   g_z[i]  = 0.f;
}

// ---------- kernel 1: Q/K/V node projections (blockIdx.y selects which) ----------
__global__ void __launch_bounds__(TPB, 2)
node_qkv_kernel(const float* __restrict__ v,
                const float* __restrict__ Wq, const float* __restrict__ bq,
                const float* __restrict__ Wk, const float* __restrict__ bk,
                const float* __restrict__ Wv, const float* __restrict__ bv,
                int N) {
    extern __shared__ float smem[];
    float* sA = smem;
    float* sB = smem + BM * SAS;
    int tid = threadIdx.x;
    int tx = tid & 15, ty = tid >> 4;

    const float* W; const float* bias; float* out;
    if      (blockIdx.y == 0) { W = Wq; bias = bq; out = g_Q; }
    else if (blockIdx.y == 1) { W = Wk; bias = bk; out = g_K; }
    else                      { W = Wv; bias = bv; out = g_V; }

    int mb = blockIdx.x * BM;
    load_tiles(v, N, mb, W, sA, sB, tid);
    __syncthreads();

    ull acc[4][4];
    #pragma unroll
    for (int i = 0; i < 4; i++)
        #pragma unroll
        for (int j = 0; j < 4; j++) acc[i][j] = 0ull;

    gemm_core(sA, sB, ty, tx, acc);

    int n0 = tx * 8;
    float bl[8];
    #pragma unroll
    for (int j = 0; j < 8; j++) bl[j] = bias[n0 + j];

    #pragma unroll
    for (int r = 0; r < 4; r++) {
        int row = mb + ty * 4 + r;
        if (row < N) {
            float o[8];
            upk(acc[r][0], o[0], o[1]); upk(acc[r][1], o[2], o[3]);
            upk(acc[r][2], o[4], o[5]); upk(acc[r][3], o[6], o[7]);
            #pragma unroll
            for (int j = 0; j < 8; j++) o[j] += bl[j];
            float4* dst = reinterpret_cast<float4*>(out + (long)row * 128 + n0);
            dst[0] = make_float4(o[0], o[1], o[2], o[3]);
            dst[1] = make_float4(o[4], o[5], o[6], o[7]);
        }
    }
}

// ---------- kernel 2: edge projection + score + e_out + softmax numerator + scatter ----------
__global__ void __launch_bounds__(TPB, 2)
edge_kernel(const float* __restrict__ e,
            const float* __restrict__ We, const float* __restrict__ be,
            const float* __restrict__ envelope,
            const int* __restrict__ src, const int* __restrict__ dst,
            float* __restrict__ eout, int E) {
    extern __shared__ float smem[];
    float* sA = smem;
    float* sB = smem + BM * SAS;
    int tid = threadIdx.x;
    int tx = tid & 15, ty = tid >> 4;

    int mb = blockIdx.x * BM;
    load_tiles(e, E, mb, We, sA, sB, tid);
    __syncthreads();

    ull acc[4][4];
    #pragma unroll
    for (int i = 0; i < 4; i++)
        #pragma unroll
        for (int j = 0; j < 4; j++) acc[i][j] = 0ull;

    gemm_core(sA, sB, ty, tx, acc);

    int n0 = tx * 8;
    int head = tx >> 1;
    float bl[8];
    #pragma unroll
    for (int j = 0; j < 8; j++) bl[j] = be[n0 + j];

    #pragma unroll
    for (int r = 0; r < 4; r++) {
        int ed  = mb + ty * 4 + r;
        int edc = (ed < E) ? ed : (E - 1);   // clamped so all lanes stay active for shfl
        int si = src[edc];
        int di = dst[edc];

        float p[8];
        upk(acc[r][0], p[0], p[1]); upk(acc[r][1], p[2], p[3]);
        upk(acc[r][2], p[4], p[5]); upk(acc[r][3], p[6], p[7]);
        #pragma unroll
        for (int j = 0; j < 8; j++) p[j] += bl[j];

        const float4* Kp = reinterpret_cast<const float4*>(g_K + (long)si * 128 + n0);
        const float4* Qp = reinterpret_cast<const float4*>(g_Q + (long)di * 128 + n0);
        float4 k0 = Kp[0], k1 = Kp[1];
        float4 q0 = Qp[0], q1 = Qp[1];

        float sc[8];
        sc[0] = k0.x * q0.x * 0.25f * p[0];
        sc[1] = k0.y * q0.y * 0.25f * p[1];
        sc[2] = k0.z * q0.z * 0.25f * p[2];
        sc[3] = k0.w * q0.w * 0.25f * p[3];
        sc[4] = k1.x * q1.x * 0.25f * p[4];
        sc[5] = k1.y * q1.y * 0.25f * p[5];
        sc[6] = k1.z * q1.z * 0.25f * p[6];
        sc[7] = k1.w * q1.w * 0.25f * p[7];

        float part = ((sc[0] + sc[1]) + (sc[2] + sc[3])) + ((sc[4] + sc[5]) + (sc[6] + sc[7]));
        part += __shfl_xor_sync(0xFFFFFFFFu, part, 1);   // pair-sum across the 16-col head
        float s = __expf(fminf(fmaxf(part, -5.f), 5.f));

        if (ed < E) {
            // explicit edge feature output (pre-exp)
            float4* ep = reinterpret_cast<float4*>(eout + (long)ed * 128 + n0);
            ep[0] = make_float4(sc[0], sc[1], sc[2], sc[3]);
            ep[1] = make_float4(sc[4], sc[5], sc[6], sc[7]);

            float env = envelope[ed];
            float es  = env * s;
            const float4* Vp = reinterpret_cast<const float4*>(g_V + (long)si * 128 + n0);
            float4 v0 = Vp[0], v1 = Vp[1];
            float* w = g_wV + (long)di * 128 + n0;
            red_v4(w,     v0.x * es, v0.y * es, v0.z * es, v0.w * es);
            red_v4(w + 4, v1.x * es, v1.y * es, v1.z * es, v1.w * es);
            if ((tx & 1) == 0) atomicAdd(g_z + (long)di * 8 + head, s);
        }
    }
}

// ---------- kernel 3: normalize ----------
__global__ void norm_kernel(float* __restrict__ vout, int N) {
    int i = blockIdx.x * blockDim.x + threadIdx.x;
    if (i < N * 128) {
        int n = i >> 7;
        int c = i & 127;
        vout[i] = g_wV[i] / (g_z[n * 8 + (c >> 4)] + 1e-6f);
    }
}

extern "C" void kernel_launch(void* const* d_in, const int* in_sizes, int n_in,
                              void* d_out, int out_size) {
    const float* v        = (const float*)d_in[0];
    const float* e        = (const float*)d_in[1];
    const float* envelope = (const float*)d_in[2];
    const float* Wq       = (const float*)d_in[3];
    const float* bq       = (const float*)d_in[4];
    const float* Wk       = (const float*)d_in[5];
    const float* bk       = (const float*)d_in[6];
    const float* Wv       = (const float*)d_in[7];
    const float* bv       = (const float*)d_in[8];
    const float* We       = (const float*)d_in[9];
    const float* be       = (const float*)d_in[10];
    const int*   src      = (const int*)d_in[11];
    const int*   dst      = (const int*)d_in[12];

    int N = in_sizes[0] / 128;
    int E = in_sizes[11];

    float* out  = (float*)d_out;
    float* vout = out;                       // [N,H,D] first
    float* eout = out + (long)N * 128;       // [E,H,D] second

    size_t smem = (size_t)(BM * SAS + KK * BN) * sizeof(float);  // ~98.8 KB
    cudaFuncSetAttribute(node_qkv_kernel, cudaFuncAttributeMaxDynamicSharedMemorySize, (int)smem);
    cudaFuncSetAttribute(edge_kernel,     cudaFuncAttributeMaxDynamicSharedMemorySize, (int)smem);

    zero_kernel<<<(N * 128 + 255) / 256, 256>>>(N);
    node_qkv_kernel<<<dim3((N + BM - 1) / BM, 3), TPB, smem>>>(v, Wq, bq, Wk, bk, Wv, bv, N);
    edge_kernel<<<(E + BM - 1) / BM, TPB, smem>>>(e, We, be, envelope, src, dst, eout, E);
    norm_kernel<<<(N * 128 + 255) / 256, 256>>>(vout, N);
}